// round 15
// baseline (speedup 1.0000x reference)
#include <cuda_runtime.h>
#include <cuda_fp16.h>
#include <cstdint>

// ---------------------------------------------------------------------------
// Problem constants
// ---------------------------------------------------------------------------
#define M_TOK  32768
#define K_IN   1024
#define N_HID  2048
#define N_EXP  16
#define CAPACITY 32768.0f

// GEMM1 tiling: CTA 128x128, 4 warps of 64x64, BK=32 (hi+lo packed per row)
#define BM 128
#define BN 128
#define BK 32
#define NKB (K_IN / BK)        // 32
#define NBLK (N_HID / BN)      // 16
#define NSTAGE 3

#define ROUTER_BLOCKS (M_TOK / 256)     // 128 < 148 SMs: all co-resident

// ---------------------------------------------------------------------------
// Device-global scratch (fp16 planes stored as u32 = fp16x2)
// ---------------------------------------------------------------------------
__device__ uint32_t g_xh[(size_t)M_TOK * K_IN / 2];
__device__ uint32_t g_xl[(size_t)M_TOK * K_IN / 2];
__device__ uint32_t g_wh[(size_t)N_HID * K_IN / 2];   // W1^T, [n][k]
__device__ uint32_t g_wl[(size_t)N_HID * K_IN / 2];
__device__ float g_plog[(size_t)NBLK * M_TOK * N_EXP];
__device__ float g_sums[N_EXP];
__device__ unsigned int g_ctr;

// ---------------------------------------------------------------------------
// helpers
// ---------------------------------------------------------------------------
__device__ __forceinline__ uint32_t smem_to_u32(const void* p) {
    uint32_t a;
    asm("{ .reg .u64 t; cvta.to.shared.u64 t, %1; cvt.u32.u64 %0, t; }"
        : "=r"(a) : "l"(p));
    return a;
}

#define CP_ASYNC16(smem_addr, gmem_ptr) \
    asm volatile("cp.async.cg.shared.global [%0], [%1], 16;" \
        :: "r"((uint32_t)(smem_addr)), "l"(gmem_ptr))
#define CP_ASYNC_COMMIT() asm volatile("cp.async.commit_group;" ::: "memory")
#define CP_ASYNC_WAIT(n)  asm volatile("cp.async.wait_group %0;" :: "n"(n) : "memory")

__device__ __forceinline__ void ldsm_x4(
    uint32_t& r0, uint32_t& r1, uint32_t& r2, uint32_t& r3, uint32_t addr
) {
    asm volatile("ldmatrix.sync.aligned.m8n8.x4.shared.b16 {%0,%1,%2,%3}, [%4];"
        : "=r"(r0), "=r"(r1), "=r"(r2), "=r"(r3) : "r"(addr));
}

__device__ __forceinline__ void mma_f16(
    float& c0, float& c1, float& c2, float& c3,
    uint32_t a0, uint32_t a1, uint32_t a2, uint32_t a3,
    uint32_t b0, uint32_t b1
) {
    asm volatile(
        "mma.sync.aligned.m16n8k16.row.col.f32.f16.f16.f32 "
        "{%0,%1,%2,%3}, {%4,%5,%6,%7}, {%8,%9}, {%0,%1,%2,%3};"
        : "+f"(c0), "+f"(c1), "+f"(c2), "+f"(c3)
        : "r"(a0), "r"(a1), "r"(a2), "r"(a3), "r"(b0), "r"(b1));
}

__device__ __forceinline__ uint32_t pack_h2(float a, float b) {
    __half2 h = __halves2half2(__float2half_rn(a), __float2half_rn(b));
    return *(uint32_t*)&h;
}

// fp16 split, unscaled lo (subnormal-exact): v = hi + lo, residual <= |v|*2^-22
__device__ __forceinline__ void split_h(float v, float& hi, float& lo) {
    __half h = __float2half_rn(v);
    hi = __half2float(h);
    lo = v - hi;
}

// ---------------------------------------------------------------------------
// Combined prep: blocks [0, 2048) transpose+split W1 (block 0 also zeroes
// g_sums and g_ctr); blocks [2048, 2048+32768) split x into fp16 planes.
// ---------------------------------------------------------------------------
#define W1_BLOCKS 2048                   // (N_HID/32) * (K_IN/32)
#define X_BLOCKS  (M_TOK * K_IN / 4 / 256)
#define PREP_BLOCKS (W1_BLOCKS + X_BLOCKS)

__global__ __launch_bounds__(256)
void prep_kernel(const float* __restrict__ x, const float* __restrict__ W1) {
    const int bid = blockIdx.x;
    const int tid = threadIdx.x;

    if (bid < W1_BLOCKS) {
        if (bid == 0 && tid < N_EXP) g_sums[tid] = 0.0f;
        if (bid == 0 && tid == N_EXP) g_ctr = 0u;
        __shared__ float t[32][33];
        const int n0 = (bid & 63) * 32;          // N_HID/32 = 64
        const int k0 = (bid >> 6) * 32;
        #pragma unroll
        for (int i = tid; i < 1024; i += 256)
            t[i >> 5][i & 31] = W1[(size_t)(k0 + (i >> 5)) * N_HID + n0 + (i & 31)];
        __syncthreads();
        #pragma unroll
        for (int idx = tid; idx < 512; idx += 256) {
            const int pair = idx & 15;
            const int nl   = idx >> 4;
            float h0, l0, h1, l1;
            split_h(t[2 * pair][nl], h0, l0);
            split_h(t[2 * pair + 1][nl], h1, l1);
            const size_t o = ((size_t)(n0 + nl) * K_IN + k0 + 2 * pair) / 2;
            g_wh[o] = pack_h2(h0, h1);
            g_wl[o] = pack_h2(l0, l1);
        }
    } else {
        const size_t i = (size_t)(bid - W1_BLOCKS) * 256 + tid;  // float4 idx
        float4 v = ((const float4*)x)[i];
        float hx, lx, hy, ly, hz, lz, hw, lw;
        split_h(v.x, hx, lx); split_h(v.y, hy, ly);
        split_h(v.z, hz, lz); split_h(v.w, hw, lw);
        uint2 hi, lo;
        hi.x = pack_h2(hx, hy); hi.y = pack_h2(hz, hw);
        lo.x = pack_h2(lx, ly); lo.y = pack_h2(lz, lw);
        ((uint2*)g_xh)[i] = hi;
        ((uint2*)g_xl)[i] = lo;
    }
}

// ---------------------------------------------------------------------------
// GEMM1 + fused partial-logits epilogue (R11 structure, best measured).
// ---------------------------------------------------------------------------
#define A_OFF 0
#define B_OFF 16384
#define STAGE_B 32768
#define SM_W2   0
#define SM_BIAS 8192
#define SM_ST0  8704
#define GEMM_SMEM_TOTAL (SM_ST0 + NSTAGE * STAGE_B)   // 107008
#define HS_STRIDE 66   // even: float2 stores stay 8B-aligned

__device__ __forceinline__ void issue_stage(
    uint32_t st, int kb, int m0, int n0, int ch, int rbase,
    const uint32_t* __restrict__ gA, const uint32_t* __restrict__ gB, int kc
) {
    const int kseg = kb * (BK / 2);    // u32 offset
    #pragma unroll
    for (int j = 0; j < 8; j++) {
        const int row = j * 16 + rbase;
        const uint32_t so = (uint32_t)(row * 128 + ((ch ^ (row & 7)) << 4));
        CP_ASYNC16(st + A_OFF + so, gA + (size_t)(m0 + row) * (K_IN / 2) + kseg + kc);
        CP_ASYNC16(st + B_OFF + so, gB + (size_t)(n0 + row) * (K_IN / 2) + kseg + kc);
    }
    CP_ASYNC_COMMIT();
}

__global__ __launch_bounds__(128, 2)
void gemm1_fused_kernel(const float* __restrict__ bias,
                        const float* __restrict__ W2) {
    extern __shared__ char smem[];
    const uint32_t smem_base = smem_to_u32(smem);
    const int tid  = threadIdx.x;
    const int lane = tid & 31;
    const int wid  = tid >> 5;
    const int wm   = wid >> 1;          // 0..1
    const int wn   = wid & 1;           // 0..1
    const int m0   = blockIdx.y * BM;
    const int n0   = blockIdx.x * BN;

    // per-thread cp.async mapping
    const int ch    = tid & 7;
    const int rbase = tid >> 3;
    const uint32_t* gA = (ch < 4) ? g_xh : g_xl;
    const uint32_t* gB = (ch < 4) ? g_wh : g_wl;
    const int kc = (ch & 3) * 4;

    // stage W2 chunk [128][16] and bias [128]
    float* w2s = (float*)(smem + SM_W2);
    {
        #pragma unroll
        for (int j = 0; j < 4; j++) {
            const int i = j * 128 + tid;
            ((float4*)w2s)[i] = ((const float4*)(W2 + (size_t)n0 * N_EXP))[i];
        }
        if (tid < 32)
            ((float4*)(smem + SM_BIAS))[tid] = ((const float4*)(bias + n0))[tid];
    }

    uint32_t stage[NSTAGE];
    #pragma unroll
    for (int s = 0; s < NSTAGE; s++)
        stage[s] = smem_base + SM_ST0 + s * STAGE_B;

    float acc[4][8][4];
    #pragma unroll
    for (int i = 0; i < 4; i++)
        #pragma unroll
        for (int j = 0; j < 8; j++)
            #pragma unroll
            for (int q = 0; q < 4; q++) acc[i][j][q] = 0.0f;

    // ldmatrix per-lane components
    const int l7 = lane & 7;
    const int a_rloc = ((lane >> 3) & 1) * 8 + l7;
    const int a_hk   = lane >> 4;
    const int b_rloc = ((lane >> 4) & 1) * 8 + l7;
    const int b_hk   = (lane >> 3) & 1;
    const uint32_t a_rowbase = (uint32_t)((wm * 64 + a_rloc) * 128);
    const uint32_t b_rowbase = (uint32_t)((wn * 64 + b_rloc) * 128);

    issue_stage(stage[0], 0, m0, n0, ch, rbase, gA, gB, kc);
    issue_stage(stage[1], 1, m0, n0, ch, rbase, gA, gB, kc);

    int cur = 0;
    for (int kb = 0; kb < NKB; kb++) {
        if (kb == NKB - 1) { CP_ASYNC_WAIT(0); } else { CP_ASYNC_WAIT(1); }
        __syncthreads();

        const uint32_t st = stage[cur];
        #pragma unroll
        for (int s = 0; s < 2; s++) {
            const uint32_t a_sw = (uint32_t)(((s * 2 + a_hk) ^ l7) << 4);
            const uint32_t b_sw = (uint32_t)(((s * 2 + b_hk) ^ l7) << 4);
            uint32_t Bh[8][2], Bl[8][2];
            #pragma unroll
            for (int q = 0; q < 4; q++) {
                const uint32_t addr = st + B_OFF + b_rowbase
                                    + (uint32_t)(q * 16 * 128) + b_sw;
                ldsm_x4(Bh[2*q][0], Bh[2*q][1], Bh[2*q+1][0], Bh[2*q+1][1], addr);
                ldsm_x4(Bl[2*q][0], Bl[2*q][1], Bl[2*q+1][0], Bl[2*q+1][1], addr ^ 64);
            }
            #pragma unroll
            for (int mt = 0; mt < 4; mt++) {
                const uint32_t addr = st + A_OFF + a_rowbase
                                    + (uint32_t)(mt * 16 * 128) + a_sw;
                uint32_t Ah[4], Al[4];
                ldsm_x4(Ah[0], Ah[1], Ah[2], Ah[3], addr);
                ldsm_x4(Al[0], Al[1], Al[2], Al[3], addr ^ 64);
                #pragma unroll
                for (int nt = 0; nt < 8; nt++) {
                    float* c = acc[mt][nt];
                    mma_f16(c[0], c[1], c[2], c[3],
                            Ah[0], Ah[1], Ah[2], Ah[3], Bh[nt][0], Bh[nt][1]);
                    mma_f16(c[0], c[1], c[2], c[3],
                            Ah[0], Ah[1], Ah[2], Ah[3], Bl[nt][0], Bl[nt][1]);
                    mma_f16(c[0], c[1], c[2], c[3],
                            Al[0], Al[1], Al[2], Al[3], Bh[nt][0], Bh[nt][1]);
                }
            }
            if (s == 0 && kb + 2 < NKB) {
                int nxt = cur + 2; if (nxt >= NSTAGE) nxt -= NSTAGE;
                issue_stage(stage[nxt], kb + 2, m0, n0, ch, rbase, gA, gB, kc);
            }
        }
        cur++; if (cur >= NSTAGE) cur = 0;
    }
    __syncthreads();

    // ---- epilogue: two half-passes through hs[128][HS_STRIDE] ----
    float* hs = (float*)(smem + SM_ST0);
    const float* bs = (const float*)(smem + SM_BIAS);
    const int gr = lane >> 2;
    const int tg = lane & 3;

    unsigned long long plp[8];
    #pragma unroll
    for (int q = 0; q < 8; q++) plp[q] = 0ull;

    #pragma unroll
    for (int chh = 0; chh < 2; chh++) {
        if (wn == chh) {
            #pragma unroll
            for (int mt = 0; mt < 4; mt++) {
                const int r0 = wm * 64 + mt * 16 + gr;
                #pragma unroll
                for (int nt = 0; nt < 8; nt++) {
                    const int cl = nt * 8 + tg * 2;
                    const int cn = chh * 64 + cl;
                    const float b0 = bs[cn], b1 = bs[cn + 1];
                    const float* c = acc[mt][nt];
                    float2 v0, v1;
                    v0.x = fmaxf(c[0] + b0, 0.0f);
                    v0.y = fmaxf(c[1] + b1, 0.0f);
                    v1.x = fmaxf(c[2] + b0, 0.0f);
                    v1.y = fmaxf(c[3] + b1, 0.0f);
                    *(float2*)&hs[(size_t)r0 * HS_STRIDE + cl] = v0;
                    *(float2*)&hs[(size_t)(r0 + 8) * HS_STRIDE + cl] = v1;
                }
            }
        }
        __syncthreads();
        const float* hrow = &hs[(size_t)tid * HS_STRIDE];
        #pragma unroll 4
        for (int j = 0; j < 64; j++) {
            const float hv = hrow[j];
            unsigned long long hp;
            asm("mov.b64 %0, {%1, %1};" : "=l"(hp) : "f"(hv));
            const unsigned long long* w =
                (const unsigned long long*)&w2s[(chh * 64 + j) * N_EXP];
            #pragma unroll
            for (int q = 0; q < 8; q++)
                asm("fma.rn.f32x2 %0, %1, %2, %0;"
                    : "+l"(plp[q]) : "l"(hp), "l"(w[q]));
        }
        __syncthreads();
    }

    float pl[N_EXP];
    #pragma unroll
    for (int q = 0; q < 8; q++)
        asm("mov.b64 {%0, %1}, %2;"
            : "=f"(pl[2 * q]), "=f"(pl[2 * q + 1]) : "l"(plp[q]));
    float* orow = &g_plog[((size_t)blockIdx.x * M_TOK + m0 + tid) * N_EXP];
    #pragma unroll
    for (int e = 0; e < N_EXP; e += 4)
        *(float4*)&orow[e] = make_float4(pl[e], pl[e+1], pl[e+2], pl[e+3]);
}

// ---------------------------------------------------------------------------
// Router + finalize fused. 128 blocks (< 148 SMs: all co-resident, so the
// software grid barrier cannot deadlock). Each block accumulates expert sums,
// publishes them, spins on g_ctr, then scales its own one-hot values (still
// in registers) and writes out exactly once.
// ---------------------------------------------------------------------------
__global__ __launch_bounds__(256)
void router_final_kernel(const float* __restrict__ b2, float* __restrict__ out) {
    __shared__ float ssum[N_EXP];
    __shared__ float sscale[N_EXP];
    const int tid = threadIdx.x;
    const size_t t = (size_t)blockIdx.x * 256 + tid;
    if (tid < N_EXP) ssum[tid] = 0.0f;
    __syncthreads();

    float lg[N_EXP];
    #pragma unroll
    for (int e = 0; e < N_EXP; e++) lg[e] = b2[e];
    #pragma unroll
    for (int nb = 0; nb < NBLK; nb++) {
        const float* p = &g_plog[((size_t)nb * M_TOK + t) * N_EXP];
        #pragma unroll
        for (int e = 0; e < N_EXP; e += 4) {
            float4 v = *(const float4*)&p[e];
            lg[e] += v.x; lg[e+1] += v.y; lg[e+2] += v.z; lg[e+3] += v.w;
        }
    }

    float best = lg[0];
    int be = 0;
    #pragma unroll
    for (int e = 1; e < N_EXP; e++)
        if (lg[e] > best) { best = lg[e]; be = e; }
    float s = 0.0f;
    #pragma unroll
    for (int e = 0; e < N_EXP; e++) s += expf(lg[e] - best);
    const float p = 1.0f / s;

    // block-level expert sums -> global
    atomicAdd(&ssum[be], p);
    __syncthreads();
    if (tid < N_EXP) atomicAdd(&g_sums[tid], ssum[tid]);

    // grid barrier: publish sums, count arrivals, spin until all 128 arrive
    __threadfence();
    if (tid == 0) {
        unsigned int arrived = atomicAdd(&g_ctr, 1u) + 1u;
        if (arrived < (unsigned int)gridDim.x) {
            volatile unsigned int* ctr = &g_ctr;
            while (*ctr < (unsigned int)gridDim.x)
                __nanosleep(64);
        }
    }
    __syncthreads();
    __threadfence();   // acquire: make all blocks' g_sums updates visible

    if (tid < N_EXP) {
        volatile float* gs = g_sums;
        sscale[tid] = CAPACITY / (gs[tid] + 1e-4f);
    }
    __syncthreads();

    const float pscaled = p * sscale[be];
    float4 o[4];
    float* of = (float*)o;
    #pragma unroll
    for (int e = 0; e < N_EXP; e++) of[e] = (e == be) ? pscaled : 0.0f;
    float4* orow = (float4*)(out + t * N_EXP);
    orow[0] = o[0]; orow[1] = o[1]; orow[2] = o[2]; orow[3] = o[3];
}

// ---------------------------------------------------------------------------
extern "C" void kernel_launch(void* const* d_in, const int* in_sizes, int n_in,
                              void* d_out, int out_size) {
    const float* x  = (const float*)d_in[0];
    const float* W1 = (const float*)d_in[1];
    const float* b1 = (const float*)d_in[2];
    const float* W2 = (const float*)d_in[3];
    const float* b2 = (const float*)d_in[4];
    float* out = (float*)d_out;

    cudaFuncSetAttribute(gemm1_fused_kernel,
                         cudaFuncAttributeMaxDynamicSharedMemorySize,
                         GEMM_SMEM_TOTAL);

    prep_kernel<<<PREP_BLOCKS, 256>>>(x, W1);                     // 1
    gemm1_fused_kernel<<<dim3(NBLK, M_TOK / BM), 128,             // 2
                         GEMM_SMEM_TOTAL>>>(b1, W2);
    router_final_kernel<<<ROUTER_BLOCKS, 256>>>(b2, out);         // 3
}

// round 16
// speedup vs baseline: 1.0051x; 1.0051x over previous
#include <cuda_runtime.h>
#include <cuda_fp16.h>
#include <cstdint>

// ---------------------------------------------------------------------------
// Problem constants
// ---------------------------------------------------------------------------
#define M_TOK  32768
#define K_IN   1024
#define N_HID  2048
#define N_EXP  16
#define CAPACITY 32768.0f

// GEMM1 tiling: CTA 128x128, 4 warps of 64x64, BK=32 (hi+lo packed per row)
#define BM 128
#define BN 128
#define BK 32
#define NKB (K_IN / BK)        // 32
#define NBLK (N_HID / BN)      // 16
#define NSTAGE 3

// ---------------------------------------------------------------------------
// Device-global scratch (fp16 planes stored as u32 = fp16x2)
// ---------------------------------------------------------------------------
__device__ uint32_t g_xh[(size_t)M_TOK * K_IN / 2];
__device__ uint32_t g_xl[(size_t)M_TOK * K_IN / 2];
__device__ uint32_t g_wh[(size_t)N_HID * K_IN / 2];   // W1^T, [n][k]
__device__ uint32_t g_wl[(size_t)N_HID * K_IN / 2];
__device__ float g_plog[(size_t)NBLK * M_TOK * N_EXP];
__device__ float g_sums[N_EXP];

// ---------------------------------------------------------------------------
// helpers
// ---------------------------------------------------------------------------
__device__ __forceinline__ uint32_t smem_to_u32(const void* p) {
    uint32_t a;
    asm("{ .reg .u64 t; cvta.to.shared.u64 t, %1; cvt.u32.u64 %0, t; }"
        : "=r"(a) : "l"(p));
    return a;
}

#define CP_ASYNC16(smem_addr, gmem_ptr) \
    asm volatile("cp.async.cg.shared.global [%0], [%1], 16;" \
        :: "r"((uint32_t)(smem_addr)), "l"(gmem_ptr))
#define CP_ASYNC_COMMIT() asm volatile("cp.async.commit_group;" ::: "memory")
#define CP_ASYNC_WAIT(n)  asm volatile("cp.async.wait_group %0;" :: "n"(n) : "memory")

__device__ __forceinline__ void ldsm_x4(
    uint32_t& r0, uint32_t& r1, uint32_t& r2, uint32_t& r3, uint32_t addr
) {
    asm volatile("ldmatrix.sync.aligned.m8n8.x4.shared.b16 {%0,%1,%2,%3}, [%4];"
        : "=r"(r0), "=r"(r1), "=r"(r2), "=r"(r3) : "r"(addr));
}

__device__ __forceinline__ void mma_f16(
    float& c0, float& c1, float& c2, float& c3,
    uint32_t a0, uint32_t a1, uint32_t a2, uint32_t a3,
    uint32_t b0, uint32_t b1
) {
    asm volatile(
        "mma.sync.aligned.m16n8k16.row.col.f32.f16.f16.f32 "
        "{%0,%1,%2,%3}, {%4,%5,%6,%7}, {%8,%9}, {%0,%1,%2,%3};"
        : "+f"(c0), "+f"(c1), "+f"(c2), "+f"(c3)
        : "r"(a0), "r"(a1), "r"(a2), "r"(a3), "r"(b0), "r"(b1));
}

__device__ __forceinline__ uint32_t pack_h2(float a, float b) {
    __half2 h = __halves2half2(__float2half_rn(a), __float2half_rn(b));
    return *(uint32_t*)&h;
}

// fp16 split, unscaled lo (subnormal-exact): v = hi + lo, residual <= |v|*2^-22
__device__ __forceinline__ void split_h(float v, float& hi, float& lo) {
    __half h = __float2half_rn(v);
    hi = __half2float(h);
    lo = v - hi;
}

// split float4 -> one hi fp16x2-pair u32x2 and one lo pair
__device__ __forceinline__ void split4(float4 v, uint32_t& h0, uint32_t& h1,
                                       uint32_t& l0, uint32_t& l1) {
    float hx, lx, hy, ly, hz, lz, hw, lw;
    split_h(v.x, hx, lx); split_h(v.y, hy, ly);
    split_h(v.z, hz, lz); split_h(v.w, hw, lw);
    h0 = pack_h2(hx, hy); h1 = pack_h2(hz, hw);
    l0 = pack_h2(lx, ly); l1 = pack_h2(lz, lw);
}

// ---------------------------------------------------------------------------
// Combined prep: blocks [0, 2048) transpose+split W1 (block 0 zeroes g_sums);
// blocks [2048, 2048+16384) split x — 8 floats/thread, 16B stores per plane.
// ---------------------------------------------------------------------------
#define W1_BLOCKS 2048                    // (N_HID/32) * (K_IN/32)
#define X_BLOCKS  (M_TOK * K_IN / 8 / 256)   // 16384
#define PREP_BLOCKS (W1_BLOCKS + X_BLOCKS)

__global__ __launch_bounds__(256)
void prep_kernel(const float* __restrict__ x, const float* __restrict__ W1) {
    const int bid = blockIdx.x;
    const int tid = threadIdx.x;

    if (bid < W1_BLOCKS) {
        if (bid == 0 && tid < N_EXP) g_sums[tid] = 0.0f;
        __shared__ float t[32][33];
        const int n0 = (bid & 63) * 32;          // N_HID/32 = 64
        const int k0 = (bid >> 6) * 32;
        #pragma unroll
        for (int i = tid; i < 1024; i += 256)
            t[i >> 5][i & 31] = W1[(size_t)(k0 + (i >> 5)) * N_HID + n0 + (i & 31)];
        __syncthreads();
        #pragma unroll
        for (int idx = tid; idx < 512; idx += 256) {
            const int pair = idx & 15;
            const int nl   = idx >> 4;
            float h0, l0, h1, l1;
            split_h(t[2 * pair][nl], h0, l0);
            split_h(t[2 * pair + 1][nl], h1, l1);
            const size_t o = ((size_t)(n0 + nl) * K_IN + k0 + 2 * pair) / 2;
            g_wh[o] = pack_h2(h0, h1);
            g_wl[o] = pack_h2(l0, l1);
        }
    } else {
        // ---- split x: 8 floats per thread, one uint4 store per plane ----
        const size_t i = (size_t)(bid - W1_BLOCKS) * 256 + tid;  // 8-float idx
        float4 v0 = ((const float4*)x)[2 * i];
        float4 v1 = ((const float4*)x)[2 * i + 1];
        uint4 hi, lo;
        split4(v0, hi.x, hi.y, lo.x, lo.y);
        split4(v1, hi.z, hi.w, lo.z, lo.w);
        ((uint4*)g_xh)[i] = hi;
        ((uint4*)g_xl)[i] = lo;
    }
}

// ---------------------------------------------------------------------------
// GEMM1 + fused partial-logits epilogue (R11/R14 structure, best measured:
// 853us, 79.8% tensor).
// ---------------------------------------------------------------------------
#define A_OFF 0
#define B_OFF 16384
#define STAGE_B 32768
#define SM_W2   0
#define SM_BIAS 8192
#define SM_ST0  8704
#define GEMM_SMEM_TOTAL (SM_ST0 + NSTAGE * STAGE_B)   // 107008
#define HS_STRIDE 66   // even: float2 stores stay 8B-aligned

__device__ __forceinline__ void issue_stage(
    uint32_t st, int kb, int m0, int n0, int ch, int rbase,
    const uint32_t* __restrict__ gA, const uint32_t* __restrict__ gB, int kc
) {
    const int kseg = kb * (BK / 2);    // u32 offset
    #pragma unroll
    for (int j = 0; j < 8; j++) {
        const int row = j * 16 + rbase;
        const uint32_t so = (uint32_t)(row * 128 + ((ch ^ (row & 7)) << 4));
        CP_ASYNC16(st + A_OFF + so, gA + (size_t)(m0 + row) * (K_IN / 2) + kseg + kc);
        CP_ASYNC16(st + B_OFF + so, gB + (size_t)(n0 + row) * (K_IN / 2) + kseg + kc);
    }
    CP_ASYNC_COMMIT();
}

__global__ __launch_bounds__(128, 2)
void gemm1_fused_kernel(const float* __restrict__ bias,
                        const float* __restrict__ W2) {
    extern __shared__ char smem[];
    const uint32_t smem_base = smem_to_u32(smem);
    const int tid  = threadIdx.x;
    const int lane = tid & 31;
    const int wid  = tid >> 5;
    const int wm   = wid >> 1;          // 0..1
    const int wn   = wid & 1;           // 0..1
    const int m0   = blockIdx.y * BM;
    const int n0   = blockIdx.x * BN;

    // per-thread cp.async mapping
    const int ch    = tid & 7;
    const int rbase = tid >> 3;
    const uint32_t* gA = (ch < 4) ? g_xh : g_xl;
    const uint32_t* gB = (ch < 4) ? g_wh : g_wl;
    const int kc = (ch & 3) * 4;

    // stage W2 chunk [128][16] and bias [128]
    float* w2s = (float*)(smem + SM_W2);
    {
        #pragma unroll
        for (int j = 0; j < 4; j++) {
            const int i = j * 128 + tid;
            ((float4*)w2s)[i] = ((const float4*)(W2 + (size_t)n0 * N_EXP))[i];
        }
        if (tid < 32)
            ((float4*)(smem + SM_BIAS))[tid] = ((const float4*)(bias + n0))[tid];
    }

    uint32_t stage[NSTAGE];
    #pragma unroll
    for (int s = 0; s < NSTAGE; s++)
        stage[s] = smem_base + SM_ST0 + s * STAGE_B;

    float acc[4][8][4];
    #pragma unroll
    for (int i = 0; i < 4; i++)
        #pragma unroll
        for (int j = 0; j < 8; j++)
            #pragma unroll
            for (int q = 0; q < 4; q++) acc[i][j][q] = 0.0f;

    // ldmatrix per-lane components
    const int l7 = lane & 7;
    const int a_rloc = ((lane >> 3) & 1) * 8 + l7;
    const int a_hk   = lane >> 4;
    const int b_rloc = ((lane >> 4) & 1) * 8 + l7;
    const int b_hk   = (lane >> 3) & 1;
    const uint32_t a_rowbase = (uint32_t)((wm * 64 + a_rloc) * 128);
    const uint32_t b_rowbase = (uint32_t)((wn * 64 + b_rloc) * 128);

    issue_stage(stage[0], 0, m0, n0, ch, rbase, gA, gB, kc);
    issue_stage(stage[1], 1, m0, n0, ch, rbase, gA, gB, kc);

    int cur = 0;
    for (int kb = 0; kb < NKB; kb++) {
        if (kb == NKB - 1) { CP_ASYNC_WAIT(0); } else { CP_ASYNC_WAIT(1); }
        __syncthreads();

        const uint32_t st = stage[cur];
        #pragma unroll
        for (int s = 0; s < 2; s++) {
            const uint32_t a_sw = (uint32_t)(((s * 2 + a_hk) ^ l7) << 4);
            const uint32_t b_sw = (uint32_t)(((s * 2 + b_hk) ^ l7) << 4);
            uint32_t Bh[8][2], Bl[8][2];
            #pragma unroll
            for (int q = 0; q < 4; q++) {
                const uint32_t addr = st + B_OFF + b_rowbase
                                    + (uint32_t)(q * 16 * 128) + b_sw;
                ldsm_x4(Bh[2*q][0], Bh[2*q][1], Bh[2*q+1][0], Bh[2*q+1][1], addr);
                ldsm_x4(Bl[2*q][0], Bl[2*q][1], Bl[2*q+1][0], Bl[2*q+1][1], addr ^ 64);
            }
            #pragma unroll
            for (int mt = 0; mt < 4; mt++) {
                const uint32_t addr = st + A_OFF + a_rowbase
                                    + (uint32_t)(mt * 16 * 128) + a_sw;
                uint32_t Ah[4], Al[4];
                ldsm_x4(Ah[0], Ah[1], Ah[2], Ah[3], addr);
                ldsm_x4(Al[0], Al[1], Al[2], Al[3], addr ^ 64);
                #pragma unroll
                for (int nt = 0; nt < 8; nt++) {
                    float* c = acc[mt][nt];
                    mma_f16(c[0], c[1], c[2], c[3],
                            Ah[0], Ah[1], Ah[2], Ah[3], Bh[nt][0], Bh[nt][1]);
                    mma_f16(c[0], c[1], c[2], c[3],
                            Ah[0], Ah[1], Ah[2], Ah[3], Bl[nt][0], Bl[nt][1]);
                    mma_f16(c[0], c[1], c[2], c[3],
                            Al[0], Al[1], Al[2], Al[3], Bh[nt][0], Bh[nt][1]);
                }
            }
            if (s == 0 && kb + 2 < NKB) {
                int nxt = cur + 2; if (nxt >= NSTAGE) nxt -= NSTAGE;
                issue_stage(stage[nxt], kb + 2, m0, n0, ch, rbase, gA, gB, kc);
            }
        }
        cur++; if (cur >= NSTAGE) cur = 0;
    }
    __syncthreads();

    // ---- epilogue: two half-passes through hs[128][HS_STRIDE] ----
    float* hs = (float*)(smem + SM_ST0);
    const float* bs = (const float*)(smem + SM_BIAS);
    const int gr = lane >> 2;
    const int tg = lane & 3;

    unsigned long long plp[8];
    #pragma unroll
    for (int q = 0; q < 8; q++) plp[q] = 0ull;

    #pragma unroll
    for (int chh = 0; chh < 2; chh++) {
        if (wn == chh) {
            #pragma unroll
            for (int mt = 0; mt < 4; mt++) {
                const int r0 = wm * 64 + mt * 16 + gr;
                #pragma unroll
                for (int nt = 0; nt < 8; nt++) {
                    const int cl = nt * 8 + tg * 2;
                    const int cn = chh * 64 + cl;
                    const float b0 = bs[cn], b1 = bs[cn + 1];
                    const float* c = acc[mt][nt];
                    float2 v0, v1;
                    v0.x = fmaxf(c[0] + b0, 0.0f);
                    v0.y = fmaxf(c[1] + b1, 0.0f);
                    v1.x = fmaxf(c[2] + b0, 0.0f);
                    v1.y = fmaxf(c[3] + b1, 0.0f);
                    *(float2*)&hs[(size_t)r0 * HS_STRIDE + cl] = v0;
                    *(float2*)&hs[(size_t)(r0 + 8) * HS_STRIDE + cl] = v1;
                }
            }
        }
        __syncthreads();
        const float* hrow = &hs[(size_t)tid * HS_STRIDE];
        #pragma unroll 4
        for (int j = 0; j < 64; j++) {
            const float hv = hrow[j];
            unsigned long long hp;
            asm("mov.b64 %0, {%1, %1};" : "=l"(hp) : "f"(hv));
            const unsigned long long* w =
                (const unsigned long long*)&w2s[(chh * 64 + j) * N_EXP];
            #pragma unroll
            for (int q = 0; q < 8; q++)
                asm("fma.rn.f32x2 %0, %1, %2, %0;"
                    : "+l"(plp[q]) : "l"(hp), "l"(w[q]));
        }
        __syncthreads();
    }

    float pl[N_EXP];
    #pragma unroll
    for (int q = 0; q < 8; q++)
        asm("mov.b64 {%0, %1}, %2;"
            : "=f"(pl[2 * q]), "=f"(pl[2 * q + 1]) : "l"(plp[q]));
    float* orow = &g_plog[((size_t)blockIdx.x * M_TOK + m0 + tid) * N_EXP];
    #pragma unroll
    for (int e = 0; e < N_EXP; e += 4)
        *(float4*)&orow[e] = make_float4(pl[e], pl[e+1], pl[e+2], pl[e+3]);
}

// ---------------------------------------------------------------------------
// Router-lite (R14 tail, measured best)
// ---------------------------------------------------------------------------
__global__ __launch_bounds__(256)
void router_lite_kernel(const float* __restrict__ b2, float* __restrict__ out) {
    __shared__ float ssum[N_EXP];
    const int tid = threadIdx.x;
    const size_t t = (size_t)blockIdx.x * 256 + tid;
    if (tid < N_EXP) ssum[tid] = 0.0f;
    __syncthreads();

    float lg[N_EXP];
    #pragma unroll
    for (int e = 0; e < N_EXP; e++) lg[e] = b2[e];
    #pragma unroll
    for (int nb = 0; nb < NBLK; nb++) {
        const float* p = &g_plog[((size_t)nb * M_TOK + t) * N_EXP];
        #pragma unroll
        for (int e = 0; e < N_EXP; e += 4) {
            float4 v = *(const float4*)&p[e];
            lg[e] += v.x; lg[e+1] += v.y; lg[e+2] += v.z; lg[e+3] += v.w;
        }
    }

    float best = lg[0];
    int be = 0;
    #pragma unroll
    for (int e = 1; e < N_EXP; e++)
        if (lg[e] > best) { best = lg[e]; be = e; }
    float s = 0.0f;
    #pragma unroll
    for (int e = 0; e < N_EXP; e++) s += expf(lg[e] - best);
    const float p = 1.0f / s;

    float4 o[4];
    float* of = (float*)o;
    #pragma unroll
    for (int e = 0; e < N_EXP; e++) of[e] = (e == be) ? p : 0.0f;
    float4* orow = (float4*)(out + t * N_EXP);
    orow[0] = o[0]; orow[1] = o[1]; orow[2] = o[2]; orow[3] = o[3];

    atomicAdd(&ssum[be], p);
    __syncthreads();
    if (tid < N_EXP) atomicAdd(&g_sums[tid], ssum[tid]);
}

// ---------------------------------------------------------------------------
__global__ void finalize_kernel(float* __restrict__ out) {
    __shared__ float sc[N_EXP];
    if (threadIdx.x < N_EXP)
        sc[threadIdx.x] = CAPACITY / (g_sums[threadIdx.x] + 1e-4f);
    __syncthreads();
    const int i = blockIdx.x * blockDim.x + threadIdx.x;
    float4 v = ((float4*)out)[i];
    const int c = (i & 3) * 4;
    v.x *= sc[c + 0];
    v.y *= sc[c + 1];
    v.z *= sc[c + 2];
    v.w *= sc[c + 3];
    ((float4*)out)[i] = v;
}

// ---------------------------------------------------------------------------
extern "C" void kernel_launch(void* const* d_in, const int* in_sizes, int n_in,
                              void* d_out, int out_size) {
    const float* x  = (const float*)d_in[0];
    const float* W1 = (const float*)d_in[1];
    const float* b1 = (const float*)d_in[2];
    const float* W2 = (const float*)d_in[3];
    const float* b2 = (const float*)d_in[4];
    float* out = (float*)d_out;

    cudaFuncSetAttribute(gemm1_fused_kernel,
                         cudaFuncAttributeMaxDynamicSharedMemorySize,
                         GEMM_SMEM_TOTAL);

    prep_kernel<<<PREP_BLOCKS, 256>>>(x, W1);                     // 1
    gemm1_fused_kernel<<<dim3(NBLK, M_TOK / BM), 128,             // 2
                         GEMM_SMEM_TOTAL>>>(b1, W2);
    router_lite_kernel<<<M_TOK / 256, 256>>>(b2, out);            // 3
    finalize_kernel<<<(M_TOK * N_EXP / 4) / 256, 256>>>(out);     // 4
}